// round 6
// baseline (speedup 1.0000x reference)
#include <cuda_runtime.h>

// Problem constants
#define NPTS        8192
#define BROWS       4096
#define KTOT        (NPTS * 3)            // 24576 floats per row
#define K4          (KTOT / 4)            // 6144 float4 per row

// Config
#define GRID_MAIN    152
#define THREADS_MAIN 512
#define NWARPS       16
#define NTILES       4
#define TILE_K4      (K4 / NTILES)        // 1536 float4 per tile
#define UNROLL       3                    // float4 per lane per tile-chunk
#define CHUNK_F4     (UNROLL * 32)        // 96 float4 per warp-chunk
#define ROWS_PER_BLK 4
#define BLKS_PER_TILE (BROWS / ROWS_PER_BLK)      // 1024
#define TOTAL_ITEMS  (NTILES * BLKS_PER_TILE)     // 4096 per wid-counter

// Per-warp-slot work-stealing counters.
__device__ unsigned g_ctr[NWARPS];

__device__ __forceinline__ float softplus_fast(float x) {
    float e = __expf(-fabsf(x));
    return fmaxf(x, 0.0f) + __logf(1.0f + e);
}

struct Sym6 { float s00, s01, s02, s11, s12, s22; };

__device__ __forceinline__ Sym6 make_sym(const float* __restrict__ w) {
    float a = softplus_fast(w[0]);
    float b = w[1];
    float c = w[2];
    float d = softplus_fast(w[3]);
    float e = w[4];
    float f = softplus_fast(w[5]);
    Sym6 s;
    s.s00 = a * a;
    s.s01 = a * b;
    s.s02 = a * c;
    s.s11 = fmaf(b, b, d * d);
    s.s12 = fmaf(b, c, d * e);
    s.s22 = fmaf(c, c, fmaf(e, e, f * f));
    return s;
}

// ---------------------------------------------------------------------------
// Init kernel: out = NPTS * bias (out is poisoned), reset steal counters.
// ---------------------------------------------------------------------------
__global__ void symm_init_kernel(const float* __restrict__ bias,
                                 float* __restrict__ out) {
    int i = blockIdx.x * blockDim.x + threadIdx.x;
    if (i < NWARPS) g_ctr[i] = 0u;
    if (i < BROWS * 3) {
        int j = i - (i / 3) * 3;
        out[i] = (float)NPTS * bias[j];
    }
}

// ---------------------------------------------------------------------------
// Main kernel: warp-level dynamic stealing over (tile, 4-row block) items.
// Each warp owns a fixed K-chunk (by wid) within each tile, so its
// register-resident W only rebuilds on tile change (monotonic per counter).
// Results go straight to out via predicated REDG from lanes 0..5 after a
// full 5-step butterfly — no smem, no __syncthreads, no epilogue.
// ---------------------------------------------------------------------------
__global__ void __launch_bounds__(THREADS_MAIN, 1)
symm_main_kernel(const float* __restrict__ x,
                 const float* __restrict__ weight,
                 float* __restrict__ out) {
    const int tid  = threadIdx.x;
    const int wid  = tid >> 5;
    const int lane = tid & 31;

    const float4* __restrict__ x4 = reinterpret_cast<const float4*>(x);

    float4 w0r[UNROLL], w1r[UNROLL], w2r[UNROLL];
    int cached_tile = -1;

    // First grab.
    unsigned item = 0u;
    if (lane == 0) item = atomicAdd(&g_ctr[wid], 1u);
    item = __shfl_sync(0xffffffffu, item, 0);

    while (item < TOTAL_ITEMS) {
        // Pipeline: issue next grab now; latency hides under this block.
        unsigned nxt = 0u;
        if (lane == 0) nxt = atomicAdd(&g_ctr[wid], 1u);

        const int tile = (int)(item >> 10);          // BLKS_PER_TILE = 1024
        const int blk  = (int)(item & 1023u);
        const int chunk4 = tile * TILE_K4 + wid * CHUNK_F4;  // warp chunk base (float4)

        if (tile != cached_tile) {
            cached_tile = tile;
#pragma unroll
            for (int i = 0; i < UNROLL; ++i) {
                const int idx = chunk4 + i * 32 + lane;
                const int k0  = 4 * idx;
                const int n0  = k0 / 3;
                const int phi = k0 - 3 * n0;

                Sym6 S0 = make_sym(weight + (size_t)n0 * 6);
                Sym6 S1 = make_sym(weight + (size_t)(n0 + 1) * 6);

                if (phi == 0) {
                    w0r[i] = make_float4(S0.s00, S0.s01, S0.s02, S1.s00);
                    w1r[i] = make_float4(S0.s01, S0.s11, S0.s12, S1.s01);
                    w2r[i] = make_float4(S0.s02, S0.s12, S0.s22, S1.s02);
                } else if (phi == 1) {
                    w0r[i] = make_float4(S0.s01, S0.s02, S1.s00, S1.s01);
                    w1r[i] = make_float4(S0.s11, S0.s12, S1.s01, S1.s11);
                    w2r[i] = make_float4(S0.s12, S0.s22, S1.s02, S1.s12);
                } else {
                    w0r[i] = make_float4(S0.s02, S1.s00, S1.s01, S1.s02);
                    w1r[i] = make_float4(S0.s12, S1.s01, S1.s11, S1.s12);
                    w2r[i] = make_float4(S0.s22, S1.s02, S1.s12, S1.s22);
                }
            }
        }

        // Process 4 contiguous rows as two R2 pairs.
        const int row0 = blk * ROWS_PER_BLK;
#pragma unroll
        for (int q = 0; q < 2; ++q) {
            const int r0 = row0 + 2 * q;
            const int r1 = r0 + 1;
            const float4* __restrict__ xr0 = x4 + (size_t)r0 * K4 + chunk4;
            const float4* __restrict__ xr1 = x4 + (size_t)r1 * K4 + chunk4;

            float4 xv0[UNROLL], xv1[UNROLL];
#pragma unroll
            for (int i = 0; i < UNROLL; ++i) {
                xv0[i] = __ldcs(&xr0[i * 32 + lane]);
                xv1[i] = __ldcs(&xr1[i * 32 + lane]);
            }

            float a0 = 0.0f, a1 = 0.0f, a2 = 0.0f;
            float b0 = 0.0f, b1 = 0.0f, b2 = 0.0f;
#pragma unroll
            for (int i = 0; i < UNROLL; ++i) {
                a0 = fmaf(xv0[i].x, w0r[i].x, a0); a0 = fmaf(xv0[i].y, w0r[i].y, a0);
                a0 = fmaf(xv0[i].z, w0r[i].z, a0); a0 = fmaf(xv0[i].w, w0r[i].w, a0);
                a1 = fmaf(xv0[i].x, w1r[i].x, a1); a1 = fmaf(xv0[i].y, w1r[i].y, a1);
                a1 = fmaf(xv0[i].z, w1r[i].z, a1); a1 = fmaf(xv0[i].w, w1r[i].w, a1);
                a2 = fmaf(xv0[i].x, w2r[i].x, a2); a2 = fmaf(xv0[i].y, w2r[i].y, a2);
                a2 = fmaf(xv0[i].z, w2r[i].z, a2); a2 = fmaf(xv0[i].w, w2r[i].w, a2);

                b0 = fmaf(xv1[i].x, w0r[i].x, b0); b0 = fmaf(xv1[i].y, w0r[i].y, b0);
                b0 = fmaf(xv1[i].z, w0r[i].z, b0); b0 = fmaf(xv1[i].w, w0r[i].w, b0);
                b1 = fmaf(xv1[i].x, w1r[i].x, b1); b1 = fmaf(xv1[i].y, w1r[i].y, b1);
                b1 = fmaf(xv1[i].z, w1r[i].z, b1); b1 = fmaf(xv1[i].w, w1r[i].w, b1);
                b2 = fmaf(xv1[i].x, w2r[i].x, b2); b2 = fmaf(xv1[i].y, w2r[i].y, b2);
                b2 = fmaf(xv1[i].z, w2r[i].z, b2); b2 = fmaf(xv1[i].w, w2r[i].w, b2);
            }

#pragma unroll
            for (int off = 16; off > 0; off >>= 1) {
                a0 += __shfl_xor_sync(0xffffffffu, a0, off);
                b0 += __shfl_xor_sync(0xffffffffu, b0, off);
                a1 += __shfl_xor_sync(0xffffffffu, a1, off);
                b1 += __shfl_xor_sync(0xffffffffu, b1, off);
                a2 += __shfl_xor_sync(0xffffffffu, a2, off);
                b2 += __shfl_xor_sync(0xffffffffu, b2, off);
            }

            // Lanes 0..5 each commit one value: (r0:a0,a1,a2), (r1:b0,b1,b2).
            if (lane < 6) {
                float v = (lane == 0) ? a0 : (lane == 1) ? a1 : (lane == 2) ? a2
                        : (lane == 3) ? b0 : (lane == 4) ? b1 : b2;
                int   rr = (lane < 3) ? r0 : r1;
                int   jj = (lane < 3) ? lane : lane - 3;
                atomicAdd(&out[rr * 3 + jj], v);
            }
        }

        nxt  = __shfl_sync(0xffffffffu, nxt, 0);
        item = nxt;
    }
}

// ---------------------------------------------------------------------------
extern "C" void kernel_launch(void* const* d_in, const int* in_sizes, int n_in,
                              void* d_out, int out_size) {
    const float* x      = (const float*)d_in[0];
    const float* weight = (const float*)d_in[1];
    const float* bias   = (const float*)d_in[2];
    float*       out    = (float*)d_out;
    (void)in_sizes; (void)n_in; (void)out_size;

    symm_init_kernel<<<(BROWS * 3 + 255) / 256, 256>>>(bias, out);
    symm_main_kernel<<<GRID_MAIN, THREADS_MAIN>>>(x, weight, out);
}